// round 15
// baseline (speedup 1.0000x reference)
#include <cuda_runtime.h>
#include <cuda_fp16.h>

// BilateralSliceApply on GB300 — Round 13.
// grid (4,16,16,8,12) f32, guide (4,1024,1024), inp/out (4,1024,1024,3).
//
// R12 (27.1us) = R10 body + occ cap 6 + RPB=2. Decomposition test:
// R13 = R10 body + occ cap 6, RPB=1 (one row/block, 4096 blocks ->
// ~92% slot utilization vs 77% at RPB=2; pixel loads overlap the stage).
// Body: split depth-2 HFMA2 trees merged by HADD2, pair-hoisted z-setup,
// one-sided z clamps, conflict-free 3xLDS.64 taps, batched .128 I/O.

#define GH 16
#define GW 16
#define GD 8
#define HH 1024
#define WW 1024
#define TPB 256
#define NXS 18               // 16 x cells + halo each side (xbase = -1)

__device__ __forceinline__ __half2 u2h(unsigned v) {
    __half2 h; asm("mov.b32 %0, %1;" : "=r"(*(unsigned*)&h) : "r"(v)); return h;
}

__global__ void __launch_bounds__(TPB, 6) bsa_kernel(
    const float* __restrict__ grid,
    const float* __restrict__ guide,
    const float* __restrict__ inp,
    float* __restrict__ out)
{
    // [xi(18)][z(8)][c12] fp16 = 3.375 KB, uint2 entries (3 per z-row)
    __shared__ uint2 PY[NXS * GD * 3];

    const int y   = blockIdx.x;
    const int b   = blockIdx.y;
    const int tid = threadIdx.x;
    const int x0  = tid * 4;

    // early pixel loads (overlap with stage LDGs)
    const size_t rowpix = (size_t)(b * HH + y) * WW;
    const float4 g4 = __ldg(reinterpret_cast<const float4*>(guide + rowpix) + tid);
    const float4* ibase = reinterpret_cast<const float4*>(inp + rowpix * 3);
    const float4 ia = __ldg(ibase + tid * 3 + 0);
    const float4 ib = __ldg(ibase + tid * 3 + 1);
    const float4 ic = __ldg(ibase + tid * 3 + 2);

    // y taps (uniform over row): gy - 0.5 = (2y-63)/128
    const int vy = 2 * y - 63;
    const int fy = vy >> 7;
    const float wy1 = (float)(vy & 127) * (1.0f / 128.0f);
    const float wy0 = 1.0f - wy1;
    const int cy0 = min(max(fy,     0), GH - 1);
    const int cy1 = min(max(fy + 1, 0), GH - 1);

    // stage PY = fp16(wy0*grid[cy0] + wy1*grid[cy1]): 432 entries
    #pragma unroll
    for (int e = tid; e < NXS * GD * 3; e += TPB) {
        const int c4 = e % 3;
        const int z  = (e / 3) & (GD - 1);
        const int xi = e / (3 * GD);
        const int gx = min(max(xi - 1, 0), GW - 1);
        const float4* g0 = reinterpret_cast<const float4*>(grid)
            + (size_t)(((b * GH + cy0) * GW + gx) * GD + z) * 3 + c4;
        const float4* g1 = reinterpret_cast<const float4*>(grid)
            + (size_t)(((b * GH + cy1) * GW + gx) * GD + z) * 3 + c4;
        const float4 a  = __ldg(g0);
        const float4 bb = __ldg(g1);
        const __half2 h0 = __floats2half2_rn(wy0 * a.x + wy1 * bb.x,
                                             wy0 * a.y + wy1 * bb.y);
        const __half2 h1 = __floats2half2_rn(wy0 * a.z + wy1 * bb.z,
                                             wy0 * a.w + wy1 * bb.w);
        uint2 v;
        v.x = *(const unsigned*)&h0;
        v.y = *(const unsigned*)&h1;
        PY[e] = v;
    }
    __syncthreads();

    // x taps: cell uniform over the thread's 4 px
    const int vx = 2 * x0 - 63;
    const int fx = vx >> 7;
    const float wx1base = (float)(vx & 127) * (1.0f / 128.0f);
    const int ebase0 = (fx + 1) * (GD * 3);
    const int ebase1 = ebase0 + GD * 3;

    const float gin[4] = {g4.x, g4.y, g4.z, g4.w};
    float o[12];

    #pragma unroll
    for (int pp = 0; pp < 4; pp += 2) {
        // hoisted z-setup + weights for the pixel pair
        int e00[2], e01[2], e10[2], e11[2];
        __half2 W00[2], W01[2], W10[2], W11[2];
        #pragma unroll
        for (int q = 0; q < 2; q++) {
            const int p = pp + q;
            const float wx1 = wx1base + (float)p * (2.0f / 128.0f);
            const float wx0 = 1.0f - wx1;
            // tz in [-0.5, 7.5] -> iz in [-1, 7]: one-sided clamps
            const float tz = fmaf(gin[p], (float)GD, -0.5f);
            const int iz = __float2int_rd(tz);
            const float wz1 = tz - (float)iz;
            const float wz0 = 1.0f - wz1;
            const int z0 = max(iz, 0);
            const int z1 = min(iz + 1, GD - 1);
            e00[q] = ebase0 + z0 * 3;  e01[q] = ebase0 + z1 * 3;
            e10[q] = ebase1 + z0 * 3;  e11[q] = ebase1 + z1 * 3;
            W00[q] = __float2half2_rn(wx0 * wz0);
            W01[q] = __float2half2_rn(wx0 * wz1);
            W10[q] = __float2half2_rn(wx1 * wz0);
            W11[q] = __float2half2_rn(wx1 * wz1);
        }

        #pragma unroll
        for (int q = 0; q < 2; q++) {
            const int p = pp + q;

            // tree A: x0 taps (depth 2)
            const uint2 qa0 = PY[e00[q]], qa1 = PY[e00[q] + 1], qa2 = PY[e00[q] + 2];
            __half2 A0 = __hmul2(u2h(qa0.x), W00[q]);
            __half2 A1 = __hmul2(u2h(qa0.y), W00[q]);
            __half2 A2 = __hmul2(u2h(qa1.x), W00[q]);
            __half2 A3 = __hmul2(u2h(qa1.y), W00[q]);
            __half2 A4 = __hmul2(u2h(qa2.x), W00[q]);
            __half2 A5 = __hmul2(u2h(qa2.y), W00[q]);
            const uint2 qb0 = PY[e01[q]], qb1 = PY[e01[q] + 1], qb2 = PY[e01[q] + 2];
            A0 = __hfma2(u2h(qb0.x), W01[q], A0);
            A1 = __hfma2(u2h(qb0.y), W01[q], A1);
            A2 = __hfma2(u2h(qb1.x), W01[q], A2);
            A3 = __hfma2(u2h(qb1.y), W01[q], A3);
            A4 = __hfma2(u2h(qb2.x), W01[q], A4);
            A5 = __hfma2(u2h(qb2.y), W01[q], A5);

            // tree B: x1 taps (depth 2, independent)
            const uint2 qc0 = PY[e10[q]], qc1 = PY[e10[q] + 1], qc2 = PY[e10[q] + 2];
            __half2 B0 = __hmul2(u2h(qc0.x), W10[q]);
            __half2 B1 = __hmul2(u2h(qc0.y), W10[q]);
            __half2 B2 = __hmul2(u2h(qc1.x), W10[q]);
            __half2 B3 = __hmul2(u2h(qc1.y), W10[q]);
            __half2 B4 = __hmul2(u2h(qc2.x), W10[q]);
            __half2 B5 = __hmul2(u2h(qc2.y), W10[q]);
            const uint2 qd0 = PY[e11[q]], qd1 = PY[e11[q] + 1], qd2 = PY[e11[q] + 2];
            B0 = __hfma2(u2h(qd0.x), W11[q], B0);
            B1 = __hfma2(u2h(qd0.y), W11[q], B1);
            B2 = __hfma2(u2h(qd1.x), W11[q], B2);
            B3 = __hfma2(u2h(qd1.y), W11[q], B3);
            B4 = __hfma2(u2h(qd2.x), W11[q], B4);
            B5 = __hfma2(u2h(qd2.y), W11[q], B5);

            // merge trees
            const __half2 a0 = __hadd2(A0, B0);
            const __half2 a1 = __hadd2(A1, B1);
            const __half2 a2 = __hadd2(A2, B2);
            const __half2 a3 = __hadd2(A3, B3);
            const __half2 a4 = __hadd2(A4, B4);
            const __half2 a5 = __hadd2(A5, B5);

            const float c0 = __low2float(a0), c1 = __high2float(a0);
            const float c2 = __low2float(a1), c3 = __high2float(a1);
            const float c4 = __low2float(a2), c5 = __high2float(a2);
            const float c6 = __low2float(a3), c7 = __high2float(a3);
            const float c8 = __low2float(a4), c9 = __high2float(a4);
            const float cA = __low2float(a5), cB = __high2float(a5);

            float i0, i1, i2;
            if (p == 0)      { i0 = ia.x; i1 = ia.y; i2 = ia.z; }
            else if (p == 1) { i0 = ia.w; i1 = ib.x; i2 = ib.y; }
            else if (p == 2) { i0 = ib.z; i1 = ib.w; i2 = ic.x; }
            else             { i0 = ic.y; i1 = ic.z; i2 = ic.w; }

            o[3 * p + 0] = c0 * i0 + c1 * i1 + c2 * i2 + c3;
            o[3 * p + 1] = c4 * i0 + c5 * i1 + c6 * i2 + c7;
            o[3 * p + 2] = c8 * i0 + c9 * i1 + cA * i2 + cB;
        }
    }

    // batched epilogue stores
    float4* obase = reinterpret_cast<float4*>(out + rowpix * 3);
    obase[tid * 3 + 0] = make_float4(o[0], o[1], o[2],  o[3]);
    obase[tid * 3 + 1] = make_float4(o[4], o[5], o[6],  o[7]);
    obase[tid * 3 + 2] = make_float4(o[8], o[9], o[10], o[11]);
}

extern "C" void kernel_launch(void* const* d_in, const int* in_sizes, int n_in,
                              void* d_out, int out_size)
{
    const float* grid  = (const float*)d_in[0];
    const float* guide = (const float*)d_in[1];
    const float* inp   = (const float*)d_in[2];
    float* out = (float*)d_out;

    const int B = in_sizes[1] / (HH * WW);  // 4

    dim3 blk(TPB, 1, 1);
    dim3 grd(HH, B, 1);                     // one block per image row (4096)
    bsa_kernel<<<grd, blk>>>(grid, guide, inp, out);
}

// round 16
// speedup vs baseline: 1.0756x; 1.0756x over previous
#include <cuda_runtime.h>
#include <cuda_fp16.h>

// BilateralSliceApply on GB300 — Round 15.
// grid (4,16,16,8,12) f32, guide (4,1024,1024), inp/out (4,1024,1024,3).
//
// R12 (27.1us, best) = R10 body + occ cap 6 + RPB=2. R13 proved RPB=2 is
// load-bearing. R15 single lever: for an (even, odd) row pair the y-cell
// pair (cy0, cy1) is PROVABLY identical (fy increments only at y=64k+32,
// between odd->even), so the stage loads each grid entry once and emits
// BOTH rows' fp16 planes -> stage global loads halved.

#define GH 16
#define GW 16
#define GD 8
#define HH 1024
#define WW 1024
#define TPB 256
#define NXS 18               // 16 x cells + halo each side (xbase = -1)
#define RPB 2                // rows per block (even-aligned pair)
#define PLANE3 (NXS * GD * 3)

__device__ __forceinline__ __half2 u2h(unsigned v) {
    __half2 h; asm("mov.b32 %0, %1;" : "=r"(*(unsigned*)&h) : "r"(v)); return h;
}

__global__ void __launch_bounds__(TPB, 6) bsa_kernel(
    const float* __restrict__ grid,
    const float* __restrict__ guide,
    const float* __restrict__ inp,
    float* __restrict__ out)
{
    __shared__ uint2 PY[RPB * PLANE3];   // 6.75 KB, [r][xi][z][c4] fp16

    const int y0  = blockIdx.x * RPB;    // even
    const int b   = blockIdx.y;
    const int tid = threadIdx.x;
    const int x0  = tid * 4;

    // x taps: cell uniform over the thread's 4 px, row-invariant
    const int vx = 2 * x0 - 63;
    const int fx = vx >> 7;
    const float wx1base = (float)(vx & 127) * (1.0f / 128.0f);
    const int ebr = (fx + 1) * (GD * 3);

    // ---- y taps for the pair: fy shared, weights differ by 2/128 ----
    const int vy = 2 * y0 - 63;
    const int fy = vy >> 7;
    const float wy1_0 = (float)(vy & 127) * (1.0f / 128.0f);
    const float wy0_0 = 1.0f - wy1_0;
    const float wy1_1 = wy1_0 + (2.0f / 128.0f);   // no wrap within pair
    const float wy0_1 = 1.0f - wy1_1;
    const int cy0 = min(max(fy,     0), GH - 1);
    const int cy1 = min(max(fy + 1, 0), GH - 1);

    // ---- stage: load grid once, emit both rows' fp16 planes ----
    #pragma unroll
    for (int e = tid; e < PLANE3; e += TPB) {
        const int c4 = e % 3;
        const int z  = (e / 3) & (GD - 1);
        const int xi = e / (3 * GD);
        const int gx = min(max(xi - 1, 0), GW - 1);
        const float4* g0 = reinterpret_cast<const float4*>(grid)
            + (size_t)(((b * GH + cy0) * GW + gx) * GD + z) * 3 + c4;
        const float4* g1 = reinterpret_cast<const float4*>(grid)
            + (size_t)(((b * GH + cy1) * GW + gx) * GD + z) * 3 + c4;
        const float4 a  = __ldg(g0);
        const float4 bb = __ldg(g1);

        // row 0 plane
        {
            const __half2 h0 = __floats2half2_rn(wy0_0 * a.x + wy1_0 * bb.x,
                                                 wy0_0 * a.y + wy1_0 * bb.y);
            const __half2 h1 = __floats2half2_rn(wy0_0 * a.z + wy1_0 * bb.z,
                                                 wy0_0 * a.w + wy1_0 * bb.w);
            uint2 v;
            v.x = *(const unsigned*)&h0;
            v.y = *(const unsigned*)&h1;
            PY[e] = v;
        }
        // row 1 plane
        {
            const __half2 h0 = __floats2half2_rn(wy0_1 * a.x + wy1_1 * bb.x,
                                                 wy0_1 * a.y + wy1_1 * bb.y);
            const __half2 h1 = __floats2half2_rn(wy0_1 * a.z + wy1_1 * bb.z,
                                                 wy0_1 * a.w + wy1_1 * bb.w);
            uint2 v;
            v.x = *(const unsigned*)&h0;
            v.y = *(const unsigned*)&h1;
            PY[PLANE3 + e] = v;
        }
    }
    __syncthreads();

    #pragma unroll
    for (int r = 0; r < RPB; r++) {
        const size_t rowpix = (size_t)(b * HH + y0 + r) * WW;
        const float4 g4 = __ldg(reinterpret_cast<const float4*>(guide + rowpix) + tid);
        const float4* ibase = reinterpret_cast<const float4*>(inp + rowpix * 3);
        const float4 ia = __ldg(ibase + tid * 3 + 0);
        const float4 ib = __ldg(ibase + tid * 3 + 1);
        const float4 ic = __ldg(ibase + tid * 3 + 2);

        const int ebase0 = r * PLANE3 + ebr;
        const int ebase1 = ebase0 + GD * 3;
        const float gin[4] = {g4.x, g4.y, g4.z, g4.w};
        float o[12];

        #pragma unroll
        for (int pp = 0; pp < 4; pp += 2) {
            // hoisted z-setup + weights for the pixel pair
            int e00[2], e01[2], e10[2], e11[2];
            __half2 W00[2], W01[2], W10[2], W11[2];
            #pragma unroll
            for (int q = 0; q < 2; q++) {
                const int p = pp + q;
                const float wx1 = wx1base + (float)p * (2.0f / 128.0f);
                const float wx0 = 1.0f - wx1;
                // tz in [-0.5, 7.5] -> iz in [-1, 7]: one-sided clamps
                const float tz = fmaf(gin[p], (float)GD, -0.5f);
                const int iz = __float2int_rd(tz);
                const float wz1 = tz - (float)iz;
                const float wz0 = 1.0f - wz1;
                const int z0 = max(iz, 0);
                const int z1 = min(iz + 1, GD - 1);
                e00[q] = ebase0 + z0 * 3;  e01[q] = ebase0 + z1 * 3;
                e10[q] = ebase1 + z0 * 3;  e11[q] = ebase1 + z1 * 3;
                W00[q] = __float2half2_rn(wx0 * wz0);
                W01[q] = __float2half2_rn(wx0 * wz1);
                W10[q] = __float2half2_rn(wx1 * wz0);
                W11[q] = __float2half2_rn(wx1 * wz1);
            }

            #pragma unroll
            for (int q = 0; q < 2; q++) {
                const int p = pp + q;

                // tree A: x0 taps (depth 2)
                const uint2 qa0 = PY[e00[q]], qa1 = PY[e00[q] + 1], qa2 = PY[e00[q] + 2];
                __half2 A0 = __hmul2(u2h(qa0.x), W00[q]);
                __half2 A1 = __hmul2(u2h(qa0.y), W00[q]);
                __half2 A2 = __hmul2(u2h(qa1.x), W00[q]);
                __half2 A3 = __hmul2(u2h(qa1.y), W00[q]);
                __half2 A4 = __hmul2(u2h(qa2.x), W00[q]);
                __half2 A5 = __hmul2(u2h(qa2.y), W00[q]);
                const uint2 qb0 = PY[e01[q]], qb1 = PY[e01[q] + 1], qb2 = PY[e01[q] + 2];
                A0 = __hfma2(u2h(qb0.x), W01[q], A0);
                A1 = __hfma2(u2h(qb0.y), W01[q], A1);
                A2 = __hfma2(u2h(qb1.x), W01[q], A2);
                A3 = __hfma2(u2h(qb1.y), W01[q], A3);
                A4 = __hfma2(u2h(qb2.x), W01[q], A4);
                A5 = __hfma2(u2h(qb2.y), W01[q], A5);

                // tree B: x1 taps (depth 2, independent)
                const uint2 qc0 = PY[e10[q]], qc1 = PY[e10[q] + 1], qc2 = PY[e10[q] + 2];
                __half2 B0 = __hmul2(u2h(qc0.x), W10[q]);
                __half2 B1 = __hmul2(u2h(qc0.y), W10[q]);
                __half2 B2 = __hmul2(u2h(qc1.x), W10[q]);
                __half2 B3 = __hmul2(u2h(qc1.y), W10[q]);
                __half2 B4 = __hmul2(u2h(qc2.x), W10[q]);
                __half2 B5 = __hmul2(u2h(qc2.y), W10[q]);
                const uint2 qd0 = PY[e11[q]], qd1 = PY[e11[q] + 1], qd2 = PY[e11[q] + 2];
                B0 = __hfma2(u2h(qd0.x), W11[q], B0);
                B1 = __hfma2(u2h(qd0.y), W11[q], B1);
                B2 = __hfma2(u2h(qd1.x), W11[q], B2);
                B3 = __hfma2(u2h(qd1.y), W11[q], B3);
                B4 = __hfma2(u2h(qd2.x), W11[q], B4);
                B5 = __hfma2(u2h(qd2.y), W11[q], B5);

                // merge trees
                const __half2 a0 = __hadd2(A0, B0);
                const __half2 a1 = __hadd2(A1, B1);
                const __half2 a2 = __hadd2(A2, B2);
                const __half2 a3 = __hadd2(A3, B3);
                const __half2 a4 = __hadd2(A4, B4);
                const __half2 a5 = __hadd2(A5, B5);

                const float c0 = __low2float(a0), c1 = __high2float(a0);
                const float c2 = __low2float(a1), c3 = __high2float(a1);
                const float c4 = __low2float(a2), c5 = __high2float(a2);
                const float c6 = __low2float(a3), c7 = __high2float(a3);
                const float c8 = __low2float(a4), c9 = __high2float(a4);
                const float cA = __low2float(a5), cB = __high2float(a5);

                float i0, i1, i2;
                if (p == 0)      { i0 = ia.x; i1 = ia.y; i2 = ia.z; }
                else if (p == 1) { i0 = ia.w; i1 = ib.x; i2 = ib.y; }
                else if (p == 2) { i0 = ib.z; i1 = ib.w; i2 = ic.x; }
                else             { i0 = ic.y; i1 = ic.z; i2 = ic.w; }

                o[3 * p + 0] = c0 * i0 + c1 * i1 + c2 * i2 + c3;
                o[3 * p + 1] = c4 * i0 + c5 * i1 + c6 * i2 + c7;
                o[3 * p + 2] = c8 * i0 + c9 * i1 + cA * i2 + cB;
            }
        }

        // batched epilogue stores for this row
        float4* obase = reinterpret_cast<float4*>(out + rowpix * 3);
        obase[tid * 3 + 0] = make_float4(o[0], o[1], o[2],  o[3]);
        obase[tid * 3 + 1] = make_float4(o[4], o[5], o[6],  o[7]);
        obase[tid * 3 + 2] = make_float4(o[8], o[9], o[10], o[11]);
    }
}

extern "C" void kernel_launch(void* const* d_in, const int* in_sizes, int n_in,
                              void* d_out, int out_size)
{
    const float* grid  = (const float*)d_in[0];
    const float* guide = (const float*)d_in[1];
    const float* inp   = (const float*)d_in[2];
    float* out = (float*)d_out;

    const int B = in_sizes[1] / (HH * WW);  // 4

    dim3 blk(TPB, 1, 1);
    dim3 grd(HH / RPB, B, 1);               // (512, 4)
    bsa_kernel<<<grd, blk>>>(grid, guide, inp, out);
}